// round 2
// baseline (speedup 1.0000x reference)
#include <cuda_runtime.h>
#include <cuda_bf16.h>

// YOLO loss: pred [16384,7,7,30] f32, target [16384,7,7,30] f32 -> scalar f32.
// Pure HBM-bound reduction (192.6 MB in, 4 B out).
//
// Single fused kernel:
//   - grid-stride over 6272 chunks of 128 cells (30 KB smem staging, coalesced
//     float4 loads), per-thread register accumulation across chunks,
//   - one block reduction at the end -> g_partials[block],
//   - last-block-done (atomic counter) reduces the 1184 partials in fixed
//     order, writes out[0] = sum / B, resets the counter for graph replay.

#define S 7
#define CELLS_PER_IMG 49
#define NCH 30
#define BATCH 16384
#define TOTAL_CELLS (BATCH * CELLS_PER_IMG)    // 802816
#define BLOCK_CELLS 128
#define NCHUNKS (TOTAL_CELLS / BLOCK_CELLS)    // 6272
#define GRID 1184                              // 148 SMs * 8
#define STEP (1.0f / 7.0f)
#define LAMBDA_COORD 5.0f
#define LAMBDA_NOOBJ 0.5f

__device__ float g_partials[GRID];
__device__ unsigned int g_count;   // zero-initialized; reset by last block

struct Box { float x1, y1, x2, y2; };

__device__ __forceinline__ Box convert_box(float x, float y, float w, float h,
                                           float gi, float gj) {
    float cx = (x + gi) * STEP;
    float cy = (y + gj) * STEP;
    Box b;
    b.x1 = fmaxf(cx - 0.5f * w, 0.0f);
    b.y1 = fmaxf(cy - 0.5f * h, 0.0f);
    b.x2 = fminf(cx + 0.5f * w, 1.0f);
    b.y2 = fminf(cy + 0.5f * h, 1.0f);
    return b;
}

__device__ __forceinline__ float iou(const Box& t, const Box& p) {
    // Faithful to reference: inter not clamped; zero if inter <= 0.
    float minx = fmaxf(t.x1, p.x1);
    float miny = fmaxf(t.y1, p.y1);
    float maxx = fminf(t.x2, p.x2);
    float maxy = fminf(t.y2, p.y2);
    float inter = (maxy - miny) * (maxx - minx);
    float uni = (p.x2 - p.x1) * (p.y2 - p.y1)
              + (t.y2 - t.y1) * (t.x2 - t.x1) - inter;
    return (inter > 0.0f) ? inter / (uni + 1e-05f) : 0.0f;
}

__global__ void __launch_bounds__(BLOCK_CELLS)
yolo_loss_fused(const float* __restrict__ pred, const float* __restrict__ tgt,
                float* __restrict__ out) {
    __shared__ float sp[BLOCK_CELLS * NCH];   // 15360 B
    __shared__ float st[BLOCK_CELLS * NCH];   // 15360 B
    __shared__ float wsum[BLOCK_CELLS / 32];
    __shared__ int s_islast;

    const int tid = threadIdx.x;
    float acc = 0.0f;

    for (int chunk = blockIdx.x; chunk < NCHUNKS; chunk += GRID) {
        const size_t base = (size_t)chunk * (BLOCK_CELLS * NCH);
        const float4* p4 = reinterpret_cast<const float4*>(pred + base);
        const float4* t4 = reinterpret_cast<const float4*>(tgt + base);
        float4* sp4 = reinterpret_cast<float4*>(sp);
        float4* st4 = reinterpret_cast<float4*>(st);
#pragma unroll
        for (int i = 0; i < 8; i++) {
            int idx = tid + i * BLOCK_CELLS;
            if (idx < BLOCK_CELLS * NCH / 4) {
                sp4[idx] = p4[idx];
                st4[idx] = t4[idx];
            }
        }
        __syncthreads();

        const float* P = sp + tid * NCH;
        const float* T = st + tid * NCH;

        const int cell = chunk * BLOCK_CELLS + tid;
        const int r = cell % CELLS_PER_IMG;
        const float gi = (float)(r / S);
        const float gj = (float)(r % S);

        const float t0 = T[0], t1 = T[1], t2 = T[2], t3 = T[3], tconf = T[4];
        Box tb = convert_box(t0, t1, t2, t3, gi, gj);
        Box pb1 = convert_box(P[0], P[1], P[2], P[3], gi, gj);
        Box pb2 = convert_box(P[5], P[6], P[7], P[8], gi, gj);
        float iou1 = iou(tb, pb1);
        float iou2 = iou(tb, pb2);

        bool sel2 = (iou1 <= iou2);
        float conf_t = sel2 ? iou2 : iou1;
        float px = sel2 ? P[5] : P[0];
        float py = sel2 ? P[6] : P[1];
        float pw = sel2 ? P[7] : P[2];
        float ph = sel2 ? P[8] : P[3];
        float pconf = sel2 ? P[9] : P[4];

        float obj = (tconf > 0.0f) ? 1.0f : 0.0f;
        float noobj = (tconf == 0.0f) ? 1.0f : 0.0f;

        float dconf = pconf - conf_t;
        float dx = px - t0, dy = py - t1, dw = pw - t2, dh = ph - t3;
        float coord = dx * dx + dy * dy + dw * dw + dh * dh;

        float cls = 0.0f;
#pragma unroll
        for (int k = 10; k < NCH; k++) {
            float d = P[k] - T[k];
            cls = fmaf(d, d, cls);
        }

        float d4 = P[4] - T[4];
        float d9 = P[9] - T[9];
        float noobj_term = d4 * d4 + d9 * d9;

        acc += obj * (dconf * dconf + LAMBDA_COORD * coord + cls)
             + LAMBDA_NOOBJ * noobj * noobj_term;

        __syncthreads();   // smem reuse next iteration
    }

    // One block reduction at the end.
#pragma unroll
    for (int off = 16; off > 0; off >>= 1)
        acc += __shfl_down_sync(0xFFFFFFFFu, acc, off);
    if ((tid & 31) == 0) wsum[tid >> 5] = acc;
    __syncthreads();

    if (tid == 0) {
        float s = wsum[0];
#pragma unroll
        for (int w = 1; w < BLOCK_CELLS / 32; w++) s += wsum[w];
        g_partials[blockIdx.x] = s;
        __threadfence();
        unsigned int old = atomicAdd(&g_count, 1u);
        s_islast = (old == GRID - 1u) ? 1 : 0;
    }
    __syncthreads();

    if (s_islast) {
        // Last block reduces all partials in fixed order (deterministic).
        volatile float* vp = g_partials;
        float s = 0.0f;
        for (int i = tid; i < GRID; i += BLOCK_CELLS) s += vp[i];
#pragma unroll
        for (int off = 16; off > 0; off >>= 1)
            s += __shfl_down_sync(0xFFFFFFFFu, s, off);
        if ((tid & 31) == 0) wsum[tid >> 5] = s;
        __syncthreads();
        if (tid == 0) {
            float tot = wsum[0];
#pragma unroll
            for (int w = 1; w < BLOCK_CELLS / 32; w++) tot += wsum[w];
            out[0] = tot * (1.0f / (float)BATCH);
            __threadfence();
            g_count = 0u;   // reset for next graph replay
        }
    }
}

extern "C" void kernel_launch(void* const* d_in, const int* in_sizes, int n_in,
                              void* d_out, int out_size) {
    const float* pred = (const float*)d_in[0];
    const float* tgt  = (const float*)d_in[1];
    float* out = (float*)d_out;
    yolo_loss_fused<<<GRID, BLOCK_CELLS>>>(pred, tgt, out);
}

// round 3
// speedup vs baseline: 1.3257x; 1.3257x over previous
#include <cuda_runtime.h>
#include <cuda_bf16.h>

// YOLO loss: pred [16384,7,7,30] f32, target [16384,7,7,30] f32 -> scalar f32.
// Pure HBM-bound reduction (192.6 MB in, 4 B out).
//
// One-shot blocks (block churn = natural load/compute overlap):
//   - each 128-thread block stages one 128-cell chunk (30720 B) into smem via
//     cp.async.cg (direct GMEM->SMEM, no register round-trip),
//   - computes per-cell loss, block-reduces, writes one partial,
//   - last-arriving block (atomic counter) reduces all 6272 partials in fixed
//     order -> out[0] = sum / B, resets counter for graph replay.

#define S 7
#define CELLS_PER_IMG 49
#define NCH 30
#define BATCH 16384
#define TOTAL_CELLS (BATCH * CELLS_PER_IMG)    // 802816
#define BLOCK_CELLS 128
#define NBLOCKS (TOTAL_CELLS / BLOCK_CELLS)    // 6272
#define STEP (1.0f / 7.0f)
#define LAMBDA_COORD 5.0f
#define LAMBDA_NOOBJ 0.5f

__device__ float g_partials[NBLOCKS];
__device__ unsigned int g_count;   // zero-init; reset by last block each launch

struct Box { float x1, y1, x2, y2; };

__device__ __forceinline__ Box convert_box(float x, float y, float w, float h,
                                           float gi, float gj) {
    float cx = (x + gi) * STEP;
    float cy = (y + gj) * STEP;
    Box b;
    b.x1 = fmaxf(cx - 0.5f * w, 0.0f);
    b.y1 = fmaxf(cy - 0.5f * h, 0.0f);
    b.x2 = fminf(cx + 0.5f * w, 1.0f);
    b.y2 = fminf(cy + 0.5f * h, 1.0f);
    return b;
}

__device__ __forceinline__ float iou(const Box& t, const Box& p) {
    // Faithful to reference: inter not clamped; zero if inter <= 0.
    float minx = fmaxf(t.x1, p.x1);
    float miny = fmaxf(t.y1, p.y1);
    float maxx = fminf(t.x2, p.x2);
    float maxy = fminf(t.y2, p.y2);
    float inter = (maxy - miny) * (maxx - minx);
    float uni = (p.x2 - p.x1) * (p.y2 - p.y1)
              + (t.y2 - t.y1) * (t.x2 - t.x1) - inter;
    return (inter > 0.0f) ? inter / (uni + 1e-05f) : 0.0f;
}

__device__ __forceinline__ void cp_async16(void* smem_dst, const void* gsrc) {
    unsigned int saddr = (unsigned int)__cvta_generic_to_shared(smem_dst);
    asm volatile("cp.async.cg.shared.global [%0], [%1], 16;\n"
                 :: "r"(saddr), "l"(gsrc) : "memory");
}

__global__ void __launch_bounds__(BLOCK_CELLS)
yolo_loss_main(const float* __restrict__ pred, const float* __restrict__ tgt,
               float* __restrict__ out) {
    __shared__ float sp[BLOCK_CELLS * NCH];   // 15360 B
    __shared__ float st[BLOCK_CELLS * NCH];   // 15360 B
    __shared__ float wsum[BLOCK_CELLS / 32];
    __shared__ int s_islast;

    const int tid = threadIdx.x;
    const int blk = blockIdx.x;
    const size_t base = (size_t)blk * (BLOCK_CELLS * NCH);

    // Stage via cp.async: 960 float4 per tensor; thread t copies indices
    // t, t+128, ... (coalesced 2048B per step across the block).
    const float4* p4 = reinterpret_cast<const float4*>(pred + base);
    const float4* t4 = reinterpret_cast<const float4*>(tgt + base);
    float4* sp4 = reinterpret_cast<float4*>(sp);
    float4* st4 = reinterpret_cast<float4*>(st);
#pragma unroll
    for (int i = 0; i < 8; i++) {
        int idx = tid + i * BLOCK_CELLS;
        if (idx < BLOCK_CELLS * NCH / 4) {
            cp_async16(&sp4[idx], &p4[idx]);
            cp_async16(&st4[idx], &t4[idx]);
        }
    }
    asm volatile("cp.async.commit_group;\n" ::: "memory");
    asm volatile("cp.async.wait_group 0;\n" ::: "memory");
    __syncthreads();

    const float* P = sp + tid * NCH;
    const float* T = st + tid * NCH;

    const int cell = blk * BLOCK_CELLS + tid;
    const int r = cell % CELLS_PER_IMG;
    const float gi = (float)(r / S);
    const float gj = (float)(r % S);

    const float t0 = T[0], t1 = T[1], t2 = T[2], t3 = T[3], tconf = T[4];
    Box tb = convert_box(t0, t1, t2, t3, gi, gj);
    Box pb1 = convert_box(P[0], P[1], P[2], P[3], gi, gj);
    Box pb2 = convert_box(P[5], P[6], P[7], P[8], gi, gj);
    float iou1 = iou(tb, pb1);
    float iou2 = iou(tb, pb2);

    bool sel2 = (iou1 <= iou2);
    float conf_t = sel2 ? iou2 : iou1;
    float px = sel2 ? P[5] : P[0];
    float py = sel2 ? P[6] : P[1];
    float pw = sel2 ? P[7] : P[2];
    float ph = sel2 ? P[8] : P[3];
    float pconf = sel2 ? P[9] : P[4];

    float obj = (tconf > 0.0f) ? 1.0f : 0.0f;
    float noobj = (tconf == 0.0f) ? 1.0f : 0.0f;

    float dconf = pconf - conf_t;
    float dx = px - t0, dy = py - t1, dw = pw - t2, dh = ph - t3;
    float coord = dx * dx + dy * dy + dw * dw + dh * dh;

    float cls = 0.0f;
#pragma unroll
    for (int k = 10; k < NCH; k++) {
        float d = P[k] - T[k];
        cls = fmaf(d, d, cls);
    }

    float d4 = P[4] - T[4];
    float d9 = P[9] - T[9];
    float noobj_term = d4 * d4 + d9 * d9;

    float L = obj * (dconf * dconf + LAMBDA_COORD * coord + cls)
            + LAMBDA_NOOBJ * noobj * noobj_term;

    // Block reduction.
#pragma unroll
    for (int off = 16; off > 0; off >>= 1)
        L += __shfl_down_sync(0xFFFFFFFFu, L, off);
    if ((tid & 31) == 0) wsum[tid >> 5] = L;
    __syncthreads();

    if (tid == 0) {
        float s = wsum[0];
#pragma unroll
        for (int w = 1; w < BLOCK_CELLS / 32; w++) s += wsum[w];
        g_partials[blk] = s;
        __threadfence();
        unsigned int old = atomicAdd(&g_count, 1u);
        s_islast = (old == NBLOCKS - 1u) ? 1 : 0;
    }
    __syncthreads();

    if (s_islast) {
        // Deterministic: fixed-order reduction of all partials by one block.
        volatile float* vp = g_partials;
        float s = 0.0f;
#pragma unroll 7
        for (int i = tid; i < NBLOCKS; i += BLOCK_CELLS) s += vp[i];
#pragma unroll
        for (int off = 16; off > 0; off >>= 1)
            s += __shfl_down_sync(0xFFFFFFFFu, s, off);
        if ((tid & 31) == 0) wsum[tid >> 5] = s;
        __syncthreads();
        if (tid == 0) {
            float tot = wsum[0];
#pragma unroll
            for (int w = 1; w < BLOCK_CELLS / 32; w++) tot += wsum[w];
            out[0] = tot * (1.0f / (float)BATCH);
            __threadfence();
            g_count = 0u;   // reset for next graph replay
        }
    }
}

extern "C" void kernel_launch(void* const* d_in, const int* in_sizes, int n_in,
                              void* d_out, int out_size) {
    const float* pred = (const float*)d_in[0];
    const float* tgt  = (const float*)d_in[1];
    float* out = (float*)d_out;
    yolo_loss_main<<<NBLOCKS, BLOCK_CELLS>>>(pred, tgt, out);
}